// round 9
// baseline (speedup 1.0000x reference)
#include <cuda_runtime.h>
#include <cuda_fp16.h>
#include <cstdint>

// DirGCNConv:
//   xs = x @ (a*Wsd)^T ; xt = x @ ((1-a)*Wds)^T    (HMMA fp16 GEMM, fp32 acc)
//   CSR/CSC via counting sort (fused histogram + single-pass scan);
//   gather accumulates fp32, writes out once, then re-zeros the degree/bsum
//   scratch so the next call starts from the same (zeroed) state.
// Side stream: wprep -> gemm, overlapped with deg -> scan -> build.

typedef unsigned int u32;

#define MAXN 50048
#define MAXE 810000
#define D    96
#define D4   24
#define ALPHA 0.5f

// -------- static scratch (zero-initialized at module load; gather restores
// g_odeg/g_ideg/g_bsum* to zero at the end of every call) --------
__device__ int   g_odeg [MAXN];
__device__ int   g_ideg [MAXN];
__device__ int   g_startR[MAXN];
__device__ int   g_startC[MAXN];
__device__ int   g_curR [MAXN];
__device__ int   g_curC [MAXN];
__device__ int   g_bsumR[256];
__device__ int   g_bsumC[256];
__device__ int2  g_pairR[MAXE];
__device__ int2  g_pairC[MAXE];
__device__ __align__(16) __half g_wh[192 * D];   // pre-scaled fp16 weights
__device__ __align__(16) __half g_xs[MAXN * D];
__device__ __align__(16) __half g_xt[MAXN * D];

// ---------------- mma helpers ----------------

__device__ __forceinline__ u32 s2u(const void* p) {
    return (u32)__cvta_generic_to_shared(p);
}

__device__ __forceinline__ void ldsm4(u32& r0, u32& r1, u32& r2, u32& r3, u32 addr) {
    asm volatile("ldmatrix.sync.aligned.m8n8.x4.shared.b16 {%0,%1,%2,%3}, [%4];"
                 : "=r"(r0), "=r"(r1), "=r"(r2), "=r"(r3) : "r"(addr));
}

__device__ __forceinline__ void mma16816(float& c0, float& c1, float& c2, float& c3,
                                         const u32* a, const u32* b) {
    asm volatile(
        "mma.sync.aligned.m16n8k16.row.col.f32.f16.f16.f32 "
        "{%0,%1,%2,%3}, {%4,%5,%6,%7}, {%8,%9}, {%0,%1,%2,%3};"
        : "+f"(c0), "+f"(c1), "+f"(c2), "+f"(c3)
        : "r"(a[0]), "r"(a[1]), "r"(a[2]), "r"(a[3]), "r"(b[0]), "r"(b[1]));
}

// ---------------- weight prep (side stream) ----------------

__global__ void wprep_kernel(const float* __restrict__ Wsd,
                             const float* __restrict__ Wds) {
    int i = blockIdx.x * blockDim.x + threadIdx.x;
    if (i >= D * D) return;
    g_wh[i]         = __float2half_rn(ALPHA          * Wsd[i]);
    g_wh[D * D + i] = __float2half_rn((1.0f - ALPHA) * Wds[i]);
}

// ---------------- degree + fused coarse histogram ----------------
// 256 threads, 8 edges/thread via 2x int4 loads per array. Coarse bins
// (node>>8) accumulated in smem, flushed once per block -> g_bsum*.

__global__ void deg_kernel(const int* __restrict__ ei, int E) {
    __shared__ int hR[256], hC[256];
    int t = threadIdx.x;
    hR[t] = 0; hC[t] = 0;
    __syncthreads();
    int base = blockIdx.x * 2048 + t * 8;
#pragma unroll
    for (int v = 0; v < 2; v++) {
        int e0 = base + v * 4;
        if (e0 + 3 < E) {
            int4 r4 = *(const int4*)&ei[e0];
            int4 c4 = *(const int4*)&ei[E + e0];
            atomicAdd(&g_odeg[r4.x], 1); atomicAdd(&hR[r4.x >> 8], 1);
            atomicAdd(&g_odeg[r4.y], 1); atomicAdd(&hR[r4.y >> 8], 1);
            atomicAdd(&g_odeg[r4.z], 1); atomicAdd(&hR[r4.z >> 8], 1);
            atomicAdd(&g_odeg[r4.w], 1); atomicAdd(&hR[r4.w >> 8], 1);
            atomicAdd(&g_ideg[c4.x], 1); atomicAdd(&hC[c4.x >> 8], 1);
            atomicAdd(&g_ideg[c4.y], 1); atomicAdd(&hC[c4.y >> 8], 1);
            atomicAdd(&g_ideg[c4.z], 1); atomicAdd(&hC[c4.z >> 8], 1);
            atomicAdd(&g_ideg[c4.w], 1); atomicAdd(&hC[c4.w >> 8], 1);
        } else {
            for (int e = e0; e < E && e < e0 + 4; e++) {
                int r = ei[e], c = ei[E + e];
                atomicAdd(&g_odeg[r], 1); atomicAdd(&hR[r >> 8], 1);
                atomicAdd(&g_ideg[c], 1); atomicAdd(&hC[c >> 8], 1);
            }
        }
    }
    __syncthreads();
    if (hR[t]) atomicAdd(&g_bsumR[t], hR[t]);
    if (hC[t]) atomicAdd(&g_bsumC[t], hC[t]);
}

// ---------------- single-pass scan ----------------

__device__ __forceinline__ int warp_incl_scan(int v) {
#pragma unroll
    for (int off = 1; off < 32; off <<= 1) {
        int a = __shfl_up_sync(0xffffffffu, v, off);
        if ((threadIdx.x & 31) >= off) v += a;
    }
    return v;
}

__global__ void scanA_kernel(int N) {
    __shared__ int wR[8], wC[8];
    __shared__ int inclR[256], inclC[256];
    int t = threadIdx.x, lane = t & 31, wid = t >> 5;

    // phase 1: redundant scan of the 256 coarse sums
    {
        int vR = g_bsumR[t];
        int vC = g_bsumC[t];
        int sR = warp_incl_scan(vR);
        int sC = warp_incl_scan(vC);
        if (lane == 31) { wR[wid] = sR; wC[wid] = sC; }
        __syncthreads();
        if (wid == 0) {
            int aR = (lane < 8) ? wR[lane] : 0;
            int aC = (lane < 8) ? wC[lane] : 0;
            aR = warp_incl_scan(aR);
            aC = warp_incl_scan(aC);
            if (lane < 8) { wR[lane] = aR; wC[lane] = aC; }
        }
        __syncthreads();
        int offR = (wid > 0) ? wR[wid - 1] : 0;
        int offC = (wid > 0) ? wC[wid - 1] : 0;
        inclR[t] = offR + sR;
        inclC[t] = offC + sC;
    }
    __syncthreads();
    int blkOffR = (blockIdx.x > 0) ? inclR[blockIdx.x - 1] : 0;
    int blkOffC = (blockIdx.x > 0) ? inclC[blockIdx.x - 1] : 0;
    __syncthreads();

    // phase 2: local scan of this block's 256 degrees
    int i = blockIdx.x * 256 + t;
    int vR = (i < N) ? g_odeg[i] : 0;
    int vC = (i < N) ? g_ideg[i] : 0;
    int sR = warp_incl_scan(vR);
    int sC = warp_incl_scan(vC);
    if (lane == 31) { wR[wid] = sR; wC[wid] = sC; }
    __syncthreads();
    if (wid == 0) {
        int aR = (lane < 8) ? wR[lane] : 0;
        int aC = (lane < 8) ? wC[lane] : 0;
        aR = warp_incl_scan(aR);
        aC = warp_incl_scan(aC);
        if (lane < 8) { wR[lane] = aR; wC[lane] = aC; }
    }
    __syncthreads();
    int offR = (wid > 0) ? wR[wid - 1] : 0;
    int offC = (wid > 0) ? wC[wid - 1] : 0;
    if (i < N) {
        int aR = blkOffR + offR + sR - vR;
        int aC = blkOffC + offC + sC - vC;
        g_startR[i] = aR; g_curR[i] = aR;
        g_startC[i] = aC; g_curC[i] = aC;
    }
}

// ---------------- CSR/CSC build ----------------

__global__ void build_kernel(const int* __restrict__ ei, int E) {
    int e = blockIdx.x * blockDim.x + threadIdx.x;
    if (e >= E) return;
    int r = ei[e];
    int c = ei[E + e];
    float val = rsqrtf((float)g_odeg[r]) * rsqrtf((float)g_ideg[c]);
    int vb = __float_as_int(val);
    int pR = atomicAdd(&g_curR[r], 1);
    g_pairR[pR] = make_int2(c, vb);
    int pC = atomicAdd(&g_curC[c], 1);
    g_pairC[pC] = make_int2(r, vb);
}

// ---------------- HMMA GEMM: 256-node tile ----------------
#define LDH 104   // 208B row stride: conflict-free ldmatrix

__global__ void __launch_bounds__(256)
gemm_mma_kernel(const float* __restrict__ x, int N) {
    extern __shared__ __half sh[];
    __half* Xs = sh;               // [256][LDH]
    __half* Ws = sh + 256 * LDH;   // [192][LDH]

    int tid = threadIdx.x;
    int nb  = blockIdx.x * 256;

    const u32* w2 = (const u32*)g_wh;       // 192*48 half2
    for (int i = tid; i < 192 * 48; i += 256) {
        int r = i / 48, c = i % 48;
        *(u32*)&Ws[r * LDH + c * 2] = w2[i];
    }
    const float4* x4 = (const float4*)x;
    for (int i = tid; i < 256 * D4; i += 256) {
        int r = i / D4, c = i % D4;
        int n = nb + r;
        float4 v = (n < N) ? x4[n * D4 + c] : make_float4(0.f, 0.f, 0.f, 0.f);
        *(__half2*)&Xs[r * LDH + c * 4]     = __floats2half2_rn(v.x, v.y);
        *(__half2*)&Xs[r * LDH + c * 4 + 2] = __floats2half2_rn(v.z, v.w);
    }
    __syncthreads();

    int wid = tid >> 5, l = tid & 31;
    int mbase = wid * 32;

    u32 a[2][6][4];
#pragma unroll
    for (int mi = 0; mi < 2; mi++) {
        u32 a_addr = s2u(&Xs[(mbase + mi * 16 + (l & 15)) * LDH + (l >> 4) * 8]);
#pragma unroll
        for (int s = 0; s < 6; s++)
            ldsm4(a[mi][s][0], a[mi][s][1], a[mi][s][2], a[mi][s][3],
                  a_addr + s * 32);
    }

    u32 b_addr0 = s2u(&Ws[(l & 7) * LDH + (l >> 3) * 8]);

    int rq = l >> 2;
    int ccol = 2 * (l & 3);

#pragma unroll
    for (int nt = 0; nt < 24; nt++) {
        u32 b[6][2];
#pragma unroll
        for (int j = 0; j < 3; j++) {
            u32 r0, r1, r2, r3;
            ldsm4(r0, r1, r2, r3, b_addr0 + nt * 8 * LDH * 2 + j * 64);
            b[2 * j][0] = r0; b[2 * j][1] = r1;
            b[2 * j + 1][0] = r2; b[2 * j + 1][1] = r3;
        }
        int c = nt * 8 + ccol;
        __half* dst = (c < D) ? g_xs : g_xt;
        int cc = (c < D) ? c : c - D;
#pragma unroll
        for (int mi = 0; mi < 2; mi++) {
            float c0 = 0.f, c1 = 0.f, c2 = 0.f, c3 = 0.f;
#pragma unroll
            for (int s = 0; s < 6; s++)
                mma16816(c0, c1, c2, c3, a[mi][s], b[s]);
            int r0n = nb + mbase + mi * 16 + rq;
            if (r0n < N)
                *(__half2*)&dst[r0n * D + cc] = __floats2half2_rn(c0, c1);
            if (r0n + 8 < N)
                *(__half2*)&dst[(r0n + 8) * D + cc] = __floats2half2_rn(c2, c3);
        }
    }
}

// ---------------- fused gather (+ scratch re-zero for next call) -------------

__device__ __forceinline__ void acc_msg(float4& acc, float v, uint2 u) {
    float2 a = __half22float2(*(__half2*)&u.x);
    float2 b = __half22float2(*(__half2*)&u.y);
    acc.x += v * a.x; acc.y += v * a.y;
    acc.z += v * b.x; acc.w += v * b.y;
}

__device__ __forceinline__ void gather_dir(float4& acc, const int2* __restrict__ pair,
                                           const uint2* __restrict__ msg,
                                           int s, int d, int lane) {
    int j = 0;
    for (; j + 8 <= d; j += 8) {
        int2 p[8]; uint2 m[8];
#pragma unroll
        for (int k = 0; k < 8; k++) p[k] = pair[s + j + k];
#pragma unroll
        for (int k = 0; k < 8; k++) m[k] = msg[p[k].x * D4 + lane];
#pragma unroll
        for (int k = 0; k < 8; k++) acc_msg(acc, __int_as_float(p[k].y), m[k]);
    }
    if (j + 4 <= d) {
        int2 p[4]; uint2 m[4];
#pragma unroll
        for (int k = 0; k < 4; k++) p[k] = pair[s + j + k];
#pragma unroll
        for (int k = 0; k < 4; k++) m[k] = msg[p[k].x * D4 + lane];
#pragma unroll
        for (int k = 0; k < 4; k++) acc_msg(acc, __int_as_float(p[k].y), m[k]);
        j += 4;
    }
    for (; j < d; j++) {
        int2 p = pair[s + j];
        acc_msg(acc, __int_as_float(p.y), msg[p.x * D4 + lane]);
    }
}

__global__ void gather_kernel(float* __restrict__ out,
                              const float* __restrict__ b_sd,
                              const float* __restrict__ b_ds,
                              int N) {
    int gt = blockIdx.x * blockDim.x + threadIdx.x;
    int warp = gt >> 5;
    int lane = threadIdx.x & 31;

    // restore the 256 coarse bins to zero for the next call (any 256 threads)
    if (gt < 256) { g_bsumR[gt] = 0; g_bsumC[gt] = 0; }

    if (warp >= N) return;
    int n = warp;

    int sR = g_startR[n], dR = g_odeg[n];
    int sC = g_startC[n], dC = g_ideg[n];

    // restore degree arrays to zero for the next call (after reading)
    if (lane == 0) { g_odeg[n] = 0; g_ideg[n] = 0; }

    if (lane >= D4) return;

    float4 acc = make_float4(0.f, 0.f, 0.f, 0.f);
    gather_dir(acc, g_pairR, (const uint2*)g_xs, sR, dR, lane);
    gather_dir(acc, g_pairC, (const uint2*)g_xt, sC, dC, lane);

    float4 bs = ((const float4*)b_sd)[lane];
    float4 bd = ((const float4*)b_ds)[lane];
    float4 o;
    o.x = acc.x + ALPHA * bs.x + (1.0f - ALPHA) * bd.x;
    o.y = acc.y + ALPHA * bs.y + (1.0f - ALPHA) * bd.y;
    o.z = acc.z + ALPHA * bs.z + (1.0f - ALPHA) * bd.z;
    o.w = acc.w + ALPHA * bs.w + (1.0f - ALPHA) * bd.w;
    ((float4*)out)[n * D4 + lane] = o;
}

// ---------------- launch ----------------
// Side chain (s2): wprep -> gemm.  Main chain: deg -> scanA -> build.
// Join before gather. Stream/events created lazily on the first
// (non-captured) correctness call; captured calls only record/wait.

static cudaStream_t g_s2  = 0;
static cudaEvent_t  g_evA = 0, g_evB = 0;

extern "C" void kernel_launch(void* const* d_in, const int* in_sizes, int n_in,
                              void* d_out, int out_size) {
    const float* x    = (const float*)d_in[0];
    const float* Wsd  = (const float*)d_in[1];
    const float* b_sd = (const float*)d_in[2];
    const float* Wds  = (const float*)d_in[3];
    const float* b_ds = (const float*)d_in[4];
    const int*   ei   = (const int*)  d_in[5];
    float* out = (float*)d_out;

    int N = in_sizes[0] / D;
    int E = in_sizes[5] / 2;

    if (!g_s2) {
        cudaStreamCreateWithFlags(&g_s2, cudaStreamNonBlocking);
        cudaEventCreateWithFlags(&g_evA, cudaEventDisableTiming);
        cudaEventCreateWithFlags(&g_evB, cudaEventDisableTiming);
    }

    size_t smem = (size_t)(256 + 192) * LDH * sizeof(__half);   // 93184 B
    cudaFuncSetAttribute(gemm_mma_kernel,
                         cudaFuncAttributeMaxDynamicSharedMemorySize, (int)smem);

    int nScan = (N + 255) / 256;

    // fork: side chain needs nothing from main stream
    cudaEventRecord(g_evA, 0);
    cudaStreamWaitEvent(g_s2, g_evA, 0);
    wprep_kernel<<<(D * D + 255) / 256, 256, 0, g_s2>>>(Wsd, Wds);
    gemm_mma_kernel<<<(N + 255) / 256, 256, smem, g_s2>>>(x, N);
    cudaEventRecord(g_evB, g_s2);

    // main chain: graph prep (degree arrays are zero at entry — invariant
    // maintained by gather's re-zero at the end of every call)
    deg_kernel  <<<(E + 2047) / 2048, 256>>>(ei, E);
    scanA_kernel<<<nScan, 256>>>(N);
    build_kernel<<<(E + 255) / 256, 256>>>(ei, E);

    // join: gather needs gemm output + CSR/CSC
    cudaStreamWaitEvent(0, g_evB, 0);
    long long gthreads = (long long)N * 32;
    gather_kernel<<<(int)((gthreads + 255) / 256), 256>>>(out, b_sd, b_ds, N);
}

// round 10
// speedup vs baseline: 2.7109x; 2.7109x over previous
#include <cuda_runtime.h>
#include <cuda_fp16.h>
#include <cstdint>

// DirGCNConv:
//   xs = x @ (a*Wsd)^T ; xt = x @ ((1-a)*Wds)^T    (HMMA fp16 GEMM, fp32 acc)
//   CSR/CSC via counting sort (fused histogram + single-pass scan);
//   gather accumulates fp32, writes out once.
// GEMM runs on a forked stream, overlapped with graph prep (deg/scan/build).
// (Exact revert to the 92.8us Round-8 configuration.)

typedef unsigned int u32;

#define MAXN 50048
#define MAXE 810000
#define D    96
#define D4   24
#define ALPHA 0.5f

// -------- static scratch --------
__device__ int   g_odeg [MAXN];
__device__ int   g_ideg [MAXN];
__device__ int   g_startR[MAXN];
__device__ int   g_startC[MAXN];
__device__ int   g_curR [MAXN];
__device__ int   g_curC [MAXN];
__device__ int   g_bsumR[256];
__device__ int   g_bsumC[256];
__device__ int2  g_pairR[MAXE];
__device__ int2  g_pairC[MAXE];
__device__ __align__(16) __half g_wh[192 * D];   // pre-scaled fp16 weights
__device__ __align__(16) __half g_xs[MAXN * D];
__device__ __align__(16) __half g_xt[MAXN * D];

// ---------------- mma helpers ----------------

__device__ __forceinline__ u32 s2u(const void* p) {
    return (u32)__cvta_generic_to_shared(p);
}

__device__ __forceinline__ void ldsm4(u32& r0, u32& r1, u32& r2, u32& r3, u32 addr) {
    asm volatile("ldmatrix.sync.aligned.m8n8.x4.shared.b16 {%0,%1,%2,%3}, [%4];"
                 : "=r"(r0), "=r"(r1), "=r"(r2), "=r"(r3) : "r"(addr));
}

__device__ __forceinline__ void mma16816(float& c0, float& c1, float& c2, float& c3,
                                         const u32* a, const u32* b) {
    asm volatile(
        "mma.sync.aligned.m16n8k16.row.col.f32.f16.f16.f32 "
        "{%0,%1,%2,%3}, {%4,%5,%6,%7}, {%8,%9}, {%0,%1,%2,%3};"
        : "+f"(c0), "+f"(c1), "+f"(c2), "+f"(c3)
        : "r"(a[0]), "r"(a[1]), "r"(a[2]), "r"(a[3]), "r"(b[0]), "r"(b[1]));
}

// ---------------- init: fp16 weights + zero degrees + zero block sums --------

__global__ void init_kernel(const float* __restrict__ Wsd,
                            const float* __restrict__ Wds, int N) {
    int i = blockIdx.x * blockDim.x + threadIdx.x;
    if (i < D * D) {
        g_wh[i]         = __float2half_rn(ALPHA          * Wsd[i]);
        g_wh[D * D + i] = __float2half_rn((1.0f - ALPHA) * Wds[i]);
    }
    if (i < N) { g_odeg[i] = 0; g_ideg[i] = 0; }
    if (i < 256) { g_bsumR[i] = 0; g_bsumC[i] = 0; }
}

// ---------------- degree + fused coarse histogram ----------------

__global__ void deg_kernel(const int* __restrict__ ei, int E) {
    __shared__ int hR[256], hC[256];
    int t = threadIdx.x;
    hR[t] = 0; hC[t] = 0;
    __syncthreads();
    int base = blockIdx.x * 2048;
#pragma unroll
    for (int k = 0; k < 8; k++) {
        int e = base + k * 256 + t;
        if (e < E) {
            int r = ei[e];
            int c = ei[E + e];
            atomicAdd(&g_odeg[r], 1);
            atomicAdd(&g_ideg[c], 1);
            atomicAdd(&hR[r >> 8], 1);
            atomicAdd(&hC[c >> 8], 1);
        }
    }
    __syncthreads();
    if (hR[t]) atomicAdd(&g_bsumR[t], hR[t]);
    if (hC[t]) atomicAdd(&g_bsumC[t], hC[t]);
}

// ---------------- single-pass scan ----------------

__device__ __forceinline__ int warp_incl_scan(int v) {
#pragma unroll
    for (int off = 1; off < 32; off <<= 1) {
        int a = __shfl_up_sync(0xffffffffu, v, off);
        if ((threadIdx.x & 31) >= off) v += a;
    }
    return v;
}

__global__ void scanA_kernel(int N) {
    __shared__ int wR[8], wC[8];
    __shared__ int inclR[256], inclC[256];
    int t = threadIdx.x, lane = t & 31, wid = t >> 5;

    {
        int vR = g_bsumR[t];
        int vC = g_bsumC[t];
        int sR = warp_incl_scan(vR);
        int sC = warp_incl_scan(vC);
        if (lane == 31) { wR[wid] = sR; wC[wid] = sC; }
        __syncthreads();
        if (wid == 0) {
            int aR = (lane < 8) ? wR[lane] : 0;
            int aC = (lane < 8) ? wC[lane] : 0;
            aR = warp_incl_scan(aR);
            aC = warp_incl_scan(aC);
            if (lane < 8) { wR[lane] = aR; wC[lane] = aC; }
        }
        __syncthreads();
        int offR = (wid > 0) ? wR[wid - 1] : 0;
        int offC = (wid > 0) ? wC[wid - 1] : 0;
        inclR[t] = offR + sR;
        inclC[t] = offC + sC;
    }
    __syncthreads();
    int blkOffR = (blockIdx.x > 0) ? inclR[blockIdx.x - 1] : 0;
    int blkOffC = (blockIdx.x > 0) ? inclC[blockIdx.x - 1] : 0;
    __syncthreads();

    int i = blockIdx.x * 256 + t;
    int vR = (i < N) ? g_odeg[i] : 0;
    int vC = (i < N) ? g_ideg[i] : 0;
    int sR = warp_incl_scan(vR);
    int sC = warp_incl_scan(vC);
    if (lane == 31) { wR[wid] = sR; wC[wid] = sC; }
    __syncthreads();
    if (wid == 0) {
        int aR = (lane < 8) ? wR[lane] : 0;
        int aC = (lane < 8) ? wC[lane] : 0;
        aR = warp_incl_scan(aR);
        aC = warp_incl_scan(aC);
        if (lane < 8) { wR[lane] = aR; wC[lane] = aC; }
    }
    __syncthreads();
    int offR = (wid > 0) ? wR[wid - 1] : 0;
    int offC = (wid > 0) ? wC[wid - 1] : 0;
    if (i < N) {
        int aR = blkOffR + offR + sR - vR;
        int aC = blkOffC + offC + sC - vC;
        g_startR[i] = aR; g_curR[i] = aR;
        g_startC[i] = aC; g_curC[i] = aC;
    }
}

// ---------------- CSR/CSC build ----------------

__global__ void build_kernel(const int* __restrict__ ei, int E) {
    int e = blockIdx.x * blockDim.x + threadIdx.x;
    if (e >= E) return;
    int r = ei[e];
    int c = ei[E + e];
    float val = rsqrtf((float)g_odeg[r]) * rsqrtf((float)g_ideg[c]);
    int vb = __float_as_int(val);
    int pR = atomicAdd(&g_curR[r], 1);
    g_pairR[pR] = make_int2(c, vb);
    int pC = atomicAdd(&g_curC[c], 1);
    g_pairC[pC] = make_int2(r, vb);
}

// ---------------- HMMA GEMM: 256-node tile ----------------
#define LDH 104   // 208B row stride: conflict-free ldmatrix

__global__ void __launch_bounds__(256)
gemm_mma_kernel(const float* __restrict__ x, int N) {
    extern __shared__ __half sh[];
    __half* Xs = sh;               // [256][LDH]
    __half* Ws = sh + 256 * LDH;   // [192][LDH]

    int tid = threadIdx.x;
    int nb  = blockIdx.x * 256;

    const u32* w2 = (const u32*)g_wh;       // 192*48 half2
    for (int i = tid; i < 192 * 48; i += 256) {
        int r = i / 48, c = i % 48;
        *(u32*)&Ws[r * LDH + c * 2] = w2[i];
    }
    const float4* x4 = (const float4*)x;
    for (int i = tid; i < 256 * D4; i += 256) {
        int r = i / D4, c = i % D4;
        int n = nb + r;
        float4 v = (n < N) ? x4[n * D4 + c] : make_float4(0.f, 0.f, 0.f, 0.f);
        *(__half2*)&Xs[r * LDH + c * 4]     = __floats2half2_rn(v.x, v.y);
        *(__half2*)&Xs[r * LDH + c * 4 + 2] = __floats2half2_rn(v.z, v.w);
    }
    __syncthreads();

    int wid = tid >> 5, l = tid & 31;
    int mbase = wid * 32;

    u32 a[2][6][4];
#pragma unroll
    for (int mi = 0; mi < 2; mi++) {
        u32 a_addr = s2u(&Xs[(mbase + mi * 16 + (l & 15)) * LDH + (l >> 4) * 8]);
#pragma unroll
        for (int s = 0; s < 6; s++)
            ldsm4(a[mi][s][0], a[mi][s][1], a[mi][s][2], a[mi][s][3],
                  a_addr + s * 32);
    }

    u32 b_addr0 = s2u(&Ws[(l & 7) * LDH + (l >> 3) * 8]);

    int rq = l >> 2;
    int ccol = 2 * (l & 3);

#pragma unroll
    for (int nt = 0; nt < 24; nt++) {
        u32 b[6][2];
#pragma unroll
        for (int j = 0; j < 3; j++) {
            u32 r0, r1, r2, r3;
            ldsm4(r0, r1, r2, r3, b_addr0 + nt * 8 * LDH * 2 + j * 64);
            b[2 * j][0] = r0; b[2 * j][1] = r1;
            b[2 * j + 1][0] = r2; b[2 * j + 1][1] = r3;
        }
        int c = nt * 8 + ccol;
        __half* dst = (c < D) ? g_xs : g_xt;
        int cc = (c < D) ? c : c - D;
#pragma unroll
        for (int mi = 0; mi < 2; mi++) {
            float c0 = 0.f, c1 = 0.f, c2 = 0.f, c3 = 0.f;
#pragma unroll
            for (int s = 0; s < 6; s++)
                mma16816(c0, c1, c2, c3, a[mi][s], b[s]);
            int r0n = nb + mbase + mi * 16 + rq;
            if (r0n < N)
                *(__half2*)&dst[r0n * D + cc] = __floats2half2_rn(c0, c1);
            if (r0n + 8 < N)
                *(__half2*)&dst[(r0n + 8) * D + cc] = __floats2half2_rn(c2, c3);
        }
    }
}

// ---------------- fused gather ----------------

__device__ __forceinline__ void acc_msg(float4& acc, float v, uint2 u) {
    float2 a = __half22float2(*(__half2*)&u.x);
    float2 b = __half22float2(*(__half2*)&u.y);
    acc.x += v * a.x; acc.y += v * a.y;
    acc.z += v * b.x; acc.w += v * b.y;
}

__device__ __forceinline__ void gather_dir(float4& acc, const int2* __restrict__ pair,
                                           const uint2* __restrict__ msg,
                                           int s, int d, int lane) {
    int j = 0;
    for (; j + 8 <= d; j += 8) {
        int2 p[8]; uint2 m[8];
#pragma unroll
        for (int k = 0; k < 8; k++) p[k] = pair[s + j + k];
#pragma unroll
        for (int k = 0; k < 8; k++) m[k] = msg[p[k].x * D4 + lane];
#pragma unroll
        for (int k = 0; k < 8; k++) acc_msg(acc, __int_as_float(p[k].y), m[k]);
    }
    if (j + 4 <= d) {
        int2 p[4]; uint2 m[4];
#pragma unroll
        for (int k = 0; k < 4; k++) p[k] = pair[s + j + k];
#pragma unroll
        for (int k = 0; k < 4; k++) m[k] = msg[p[k].x * D4 + lane];
#pragma unroll
        for (int k = 0; k < 4; k++) acc_msg(acc, __int_as_float(p[k].y), m[k]);
        j += 4;
    }
    for (; j < d; j++) {
        int2 p = pair[s + j];
        acc_msg(acc, __int_as_float(p.y), msg[p.x * D4 + lane]);
    }
}

__global__ void gather_kernel(float* __restrict__ out,
                              const float* __restrict__ b_sd,
                              const float* __restrict__ b_ds,
                              int N) {
    int warp = (blockIdx.x * blockDim.x + threadIdx.x) >> 5;
    int lane = threadIdx.x & 31;
    if (warp >= N || lane >= D4) return;
    int n = warp;

    float4 acc = make_float4(0.f, 0.f, 0.f, 0.f);

    gather_dir(acc, g_pairR, (const uint2*)g_xs, g_startR[n], g_odeg[n], lane);
    gather_dir(acc, g_pairC, (const uint2*)g_xt, g_startC[n], g_ideg[n], lane);

    float4 bs = ((const float4*)b_sd)[lane];
    float4 bd = ((const float4*)b_ds)[lane];
    float4 o;
    o.x = acc.x + ALPHA * bs.x + (1.0f - ALPHA) * bd.x;
    o.y = acc.y + ALPHA * bs.y + (1.0f - ALPHA) * bd.y;
    o.z = acc.z + ALPHA * bs.z + (1.0f - ALPHA) * bd.z;
    o.w = acc.w + ALPHA * bs.w + (1.0f - ALPHA) * bd.w;
    ((float4*)out)[n * D4 + lane] = o;
}

// ---------------- launch ----------------
// Fork-join: gemm on a side stream, overlapped with deg/scan/build on the
// main stream. Stream/events created once on the first (non-captured)
// correctness call; captured calls only record/wait (capturable ops).

static cudaStream_t g_s2  = 0;
static cudaEvent_t  g_evA = 0, g_evB = 0;

extern "C" void kernel_launch(void* const* d_in, const int* in_sizes, int n_in,
                              void* d_out, int out_size) {
    const float* x    = (const float*)d_in[0];
    const float* Wsd  = (const float*)d_in[1];
    const float* b_sd = (const float*)d_in[2];
    const float* Wds  = (const float*)d_in[3];
    const float* b_ds = (const float*)d_in[4];
    const int*   ei   = (const int*)  d_in[5];
    float* out = (float*)d_out;

    int N = in_sizes[0] / D;
    int E = in_sizes[5] / 2;

    if (!g_s2) {
        cudaStreamCreateWithFlags(&g_s2, cudaStreamNonBlocking);
        cudaEventCreateWithFlags(&g_evA, cudaEventDisableTiming);
        cudaEventCreateWithFlags(&g_evB, cudaEventDisableTiming);
    }

    size_t smem = (size_t)(256 + 192) * LDH * sizeof(__half);   // 93184 B
    cudaFuncSetAttribute(gemm_mma_kernel,
                         cudaFuncAttributeMaxDynamicSharedMemorySize, (int)smem);

    int nScan = (N + 255) / 256;

    init_kernel<<<(N + 255) / 256, 256>>>(Wsd, Wds, N);

    // fork: gemm depends only on init
    cudaEventRecord(g_evA, 0);
    cudaStreamWaitEvent(g_s2, g_evA, 0);
    gemm_mma_kernel<<<(N + 255) / 256, 256, smem, g_s2>>>(x, N);
    cudaEventRecord(g_evB, g_s2);

    // graph prep on main stream (overlaps with gemm)
    deg_kernel  <<<(E + 2047) / 2048, 256>>>(ei, E);
    scanA_kernel<<<nScan, 256>>>(N);
    build_kernel<<<(E + 255) / 256, 256>>>(ei, E);

    // join: gather needs both
    cudaStreamWaitEvent(0, g_evB, 0);
    long long gthreads = (long long)N * 32;
    gather_kernel<<<(int)((gthreads + 255) / 256), 256>>>(out, b_sd, b_ds, N);
}

// round 11
// speedup vs baseline: 2.7702x; 1.0219x over previous
#include <cuda_runtime.h>
#include <cuda_fp16.h>
#include <cstdint>

// DirGCNConv:
//   xs = x @ (a*Wsd)^T ; xt = x @ ((1-a)*Wds)^T    (HMMA fp16 GEMM, fp32 acc)
//   CSR/CSC via counting sort (fused histogram + single-pass scan);
//   gather accumulates fp32, writes out once.
// GEMM runs on a forked stream, overlapped with graph prep (deg/scan/build).
// vs R8 baseline: build unrolled 4x (MLP), g_start removed (start = cur - deg).

typedef unsigned int u32;

#define MAXN 50048
#define MAXE 810000
#define D    96
#define D4   24
#define ALPHA 0.5f

// -------- static scratch --------
__device__ int   g_odeg [MAXN];
__device__ int   g_ideg [MAXN];
__device__ int   g_curR [MAXN];
__device__ int   g_curC [MAXN];
__device__ int   g_bsumR[256];
__device__ int   g_bsumC[256];
__device__ int2  g_pairR[MAXE];
__device__ int2  g_pairC[MAXE];
__device__ __align__(16) __half g_wh[192 * D];   // pre-scaled fp16 weights
__device__ __align__(16) __half g_xs[MAXN * D];
__device__ __align__(16) __half g_xt[MAXN * D];

// ---------------- mma helpers ----------------

__device__ __forceinline__ u32 s2u(const void* p) {
    return (u32)__cvta_generic_to_shared(p);
}

__device__ __forceinline__ void ldsm4(u32& r0, u32& r1, u32& r2, u32& r3, u32 addr) {
    asm volatile("ldmatrix.sync.aligned.m8n8.x4.shared.b16 {%0,%1,%2,%3}, [%4];"
                 : "=r"(r0), "=r"(r1), "=r"(r2), "=r"(r3) : "r"(addr));
}

__device__ __forceinline__ void mma16816(float& c0, float& c1, float& c2, float& c3,
                                         const u32* a, const u32* b) {
    asm volatile(
        "mma.sync.aligned.m16n8k16.row.col.f32.f16.f16.f32 "
        "{%0,%1,%2,%3}, {%4,%5,%6,%7}, {%8,%9}, {%0,%1,%2,%3};"
        : "+f"(c0), "+f"(c1), "+f"(c2), "+f"(c3)
        : "r"(a[0]), "r"(a[1]), "r"(a[2]), "r"(a[3]), "r"(b[0]), "r"(b[1]));
}

// ---------------- init: fp16 weights + zero degrees + zero block sums --------

__global__ void init_kernel(const float* __restrict__ Wsd,
                            const float* __restrict__ Wds, int N) {
    int i = blockIdx.x * blockDim.x + threadIdx.x;
    if (i < D * D) {
        g_wh[i]         = __float2half_rn(ALPHA          * Wsd[i]);
        g_wh[D * D + i] = __float2half_rn((1.0f - ALPHA) * Wds[i]);
    }
    if (i < N) { g_odeg[i] = 0; g_ideg[i] = 0; }
    if (i < 256) { g_bsumR[i] = 0; g_bsumC[i] = 0; }
}

// ---------------- degree + fused coarse histogram ----------------

__global__ void deg_kernel(const int* __restrict__ ei, int E) {
    __shared__ int hR[256], hC[256];
    int t = threadIdx.x;
    hR[t] = 0; hC[t] = 0;
    __syncthreads();
    int base = blockIdx.x * 2048;
#pragma unroll
    for (int k = 0; k < 8; k++) {
        int e = base + k * 256 + t;
        if (e < E) {
            int r = ei[e];
            int c = ei[E + e];
            atomicAdd(&g_odeg[r], 1);
            atomicAdd(&g_ideg[c], 1);
            atomicAdd(&hR[r >> 8], 1);
            atomicAdd(&hC[c >> 8], 1);
        }
    }
    __syncthreads();
    if (hR[t]) atomicAdd(&g_bsumR[t], hR[t]);
    if (hC[t]) atomicAdd(&g_bsumC[t], hC[t]);
}

// ---------------- single-pass scan (writes cur only; start = cur - deg) ------

__device__ __forceinline__ int warp_incl_scan(int v) {
#pragma unroll
    for (int off = 1; off < 32; off <<= 1) {
        int a = __shfl_up_sync(0xffffffffu, v, off);
        if ((threadIdx.x & 31) >= off) v += a;
    }
    return v;
}

__global__ void scanA_kernel(int N) {
    __shared__ int wR[8], wC[8];
    __shared__ int inclR[256], inclC[256];
    int t = threadIdx.x, lane = t & 31, wid = t >> 5;

    // phase 1: redundant scan of the 256 coarse sums
    {
        int vR = g_bsumR[t];
        int vC = g_bsumC[t];
        int sR = warp_incl_scan(vR);
        int sC = warp_incl_scan(vC);
        if (lane == 31) { wR[wid] = sR; wC[wid] = sC; }
        __syncthreads();
        if (wid == 0) {
            int aR = (lane < 8) ? wR[lane] : 0;
            int aC = (lane < 8) ? wC[lane] : 0;
            aR = warp_incl_scan(aR);
            aC = warp_incl_scan(aC);
            if (lane < 8) { wR[lane] = aR; wC[lane] = aC; }
        }
        __syncthreads();
        int offR = (wid > 0) ? wR[wid - 1] : 0;
        int offC = (wid > 0) ? wC[wid - 1] : 0;
        inclR[t] = offR + sR;
        inclC[t] = offC + sC;
    }
    __syncthreads();
    int blkOffR = (blockIdx.x > 0) ? inclR[blockIdx.x - 1] : 0;
    int blkOffC = (blockIdx.x > 0) ? inclC[blockIdx.x - 1] : 0;
    __syncthreads();

    // phase 2: local scan of this block's 256 degrees
    int i = blockIdx.x * 256 + t;
    int vR = (i < N) ? g_odeg[i] : 0;
    int vC = (i < N) ? g_ideg[i] : 0;
    int sR = warp_incl_scan(vR);
    int sC = warp_incl_scan(vC);
    if (lane == 31) { wR[wid] = sR; wC[wid] = sC; }
    __syncthreads();
    if (wid == 0) {
        int aR = (lane < 8) ? wR[lane] : 0;
        int aC = (lane < 8) ? wC[lane] : 0;
        aR = warp_incl_scan(aR);
        aC = warp_incl_scan(aC);
        if (lane < 8) { wR[lane] = aR; wC[lane] = aC; }
    }
    __syncthreads();
    int offR = (wid > 0) ? wR[wid - 1] : 0;
    int offC = (wid > 0) ? wC[wid - 1] : 0;
    if (i < N) {
        g_curR[i] = blkOffR + offR + sR - vR;   // exclusive start
        g_curC[i] = blkOffC + offC + sC - vC;
    }
}

// ---------------- CSR/CSC build (4 edges/thread, batched loads) --------------

__global__ void build_kernel(const int* __restrict__ ei, int E) {
    int e0 = (blockIdx.x * blockDim.x + threadIdx.x) * 4;
    if (e0 >= E) return;

    if (e0 + 4 <= E) {
        int r[4], c[4];
#pragma unroll
        for (int k = 0; k < 4; k++) r[k] = ei[e0 + k];
#pragma unroll
        for (int k = 0; k < 4; k++) c[k] = ei[E + e0 + k];
        int od[4], id[4];
#pragma unroll
        for (int k = 0; k < 4; k++) od[k] = g_odeg[r[k]];
#pragma unroll
        for (int k = 0; k < 4; k++) id[k] = g_ideg[c[k]];
#pragma unroll
        for (int k = 0; k < 4; k++) {
            float val = rsqrtf((float)od[k]) * rsqrtf((float)id[k]);
            int vb = __float_as_int(val);
            int pR = atomicAdd(&g_curR[r[k]], 1);
            g_pairR[pR] = make_int2(c[k], vb);
            int pC = atomicAdd(&g_curC[c[k]], 1);
            g_pairC[pC] = make_int2(r[k], vb);
        }
    } else {
        for (int e = e0; e < E; e++) {
            int r = ei[e];
            int c = ei[E + e];
            float val = rsqrtf((float)g_odeg[r]) * rsqrtf((float)g_ideg[c]);
            int vb = __float_as_int(val);
            int pR = atomicAdd(&g_curR[r], 1);
            g_pairR[pR] = make_int2(c, vb);
            int pC = atomicAdd(&g_curC[c], 1);
            g_pairC[pC] = make_int2(r, vb);
        }
    }
}

// ---------------- HMMA GEMM: 256-node tile ----------------
#define LDH 104   // 208B row stride: conflict-free ldmatrix

__global__ void __launch_bounds__(256)
gemm_mma_kernel(const float* __restrict__ x, int N) {
    extern __shared__ __half sh[];
    __half* Xs = sh;               // [256][LDH]
    __half* Ws = sh + 256 * LDH;   // [192][LDH]

    int tid = threadIdx.x;
    int nb  = blockIdx.x * 256;

    const u32* w2 = (const u32*)g_wh;       // 192*48 half2
    for (int i = tid; i < 192 * 48; i += 256) {
        int r = i / 48, c = i % 48;
        *(u32*)&Ws[r * LDH + c * 2] = w2[i];
    }
    const float4* x4 = (const float4*)x;
    for (int i = tid; i < 256 * D4; i += 256) {
        int r = i / D4, c = i % D4;
        int n = nb + r;
        float4 v = (n < N) ? x4[n * D4 + c] : make_float4(0.f, 0.f, 0.f, 0.f);
        *(__half2*)&Xs[r * LDH + c * 4]     = __floats2half2_rn(v.x, v.y);
        *(__half2*)&Xs[r * LDH + c * 4 + 2] = __floats2half2_rn(v.z, v.w);
    }
    __syncthreads();

    int wid = tid >> 5, l = tid & 31;
    int mbase = wid * 32;

    u32 a[2][6][4];
#pragma unroll
    for (int mi = 0; mi < 2; mi++) {
        u32 a_addr = s2u(&Xs[(mbase + mi * 16 + (l & 15)) * LDH + (l >> 4) * 8]);
#pragma unroll
        for (int s = 0; s < 6; s++)
            ldsm4(a[mi][s][0], a[mi][s][1], a[mi][s][2], a[mi][s][3],
                  a_addr + s * 32);
    }

    u32 b_addr0 = s2u(&Ws[(l & 7) * LDH + (l >> 3) * 8]);

    int rq = l >> 2;
    int ccol = 2 * (l & 3);

#pragma unroll
    for (int nt = 0; nt < 24; nt++) {
        u32 b[6][2];
#pragma unroll
        for (int j = 0; j < 3; j++) {
            u32 r0, r1, r2, r3;
            ldsm4(r0, r1, r2, r3, b_addr0 + nt * 8 * LDH * 2 + j * 64);
            b[2 * j][0] = r0; b[2 * j][1] = r1;
            b[2 * j + 1][0] = r2; b[2 * j + 1][1] = r3;
        }
        int c = nt * 8 + ccol;
        __half* dst = (c < D) ? g_xs : g_xt;
        int cc = (c < D) ? c : c - D;
#pragma unroll
        for (int mi = 0; mi < 2; mi++) {
            float c0 = 0.f, c1 = 0.f, c2 = 0.f, c3 = 0.f;
#pragma unroll
            for (int s = 0; s < 6; s++)
                mma16816(c0, c1, c2, c3, a[mi][s], b[s]);
            int r0n = nb + mbase + mi * 16 + rq;
            if (r0n < N)
                *(__half2*)&dst[r0n * D + cc] = __floats2half2_rn(c0, c1);
            if (r0n + 8 < N)
                *(__half2*)&dst[(r0n + 8) * D + cc] = __floats2half2_rn(c2, c3);
        }
    }
}

// ---------------- fused gather ----------------

__device__ __forceinline__ void acc_msg(float4& acc, float v, uint2 u) {
    float2 a = __half22float2(*(__half2*)&u.x);
    float2 b = __half22float2(*(__half2*)&u.y);
    acc.x += v * a.x; acc.y += v * a.y;
    acc.z += v * b.x; acc.w += v * b.y;
}

__device__ __forceinline__ void gather_dir(float4& acc, const int2* __restrict__ pair,
                                           const uint2* __restrict__ msg,
                                           int s, int d, int lane) {
    int j = 0;
    for (; j + 8 <= d; j += 8) {
        int2 p[8]; uint2 m[8];
#pragma unroll
        for (int k = 0; k < 8; k++) p[k] = pair[s + j + k];
#pragma unroll
        for (int k = 0; k < 8; k++) m[k] = msg[p[k].x * D4 + lane];
#pragma unroll
        for (int k = 0; k < 8; k++) acc_msg(acc, __int_as_float(p[k].y), m[k]);
    }
    if (j + 4 <= d) {
        int2 p[4]; uint2 m[4];
#pragma unroll
        for (int k = 0; k < 4; k++) p[k] = pair[s + j + k];
#pragma unroll
        for (int k = 0; k < 4; k++) m[k] = msg[p[k].x * D4 + lane];
#pragma unroll
        for (int k = 0; k < 4; k++) acc_msg(acc, __int_as_float(p[k].y), m[k]);
        j += 4;
    }
    for (; j < d; j++) {
        int2 p = pair[s + j];
        acc_msg(acc, __int_as_float(p.y), msg[p.x * D4 + lane]);
    }
}

__global__ void gather_kernel(float* __restrict__ out,
                              const float* __restrict__ b_sd,
                              const float* __restrict__ b_ds,
                              int N) {
    int warp = (blockIdx.x * blockDim.x + threadIdx.x) >> 5;
    int lane = threadIdx.x & 31;
    if (warp >= N || lane >= D4) return;
    int n = warp;

    int dR = g_odeg[n];
    int dC = g_ideg[n];
    int sR = g_curR[n] - dR;   // build advanced cur to start+deg
    int sC = g_curC[n] - dC;

    float4 acc = make_float4(0.f, 0.f, 0.f, 0.f);
    gather_dir(acc, g_pairR, (const uint2*)g_xs, sR, dR, lane);
    gather_dir(acc, g_pairC, (const uint2*)g_xt, sC, dC, lane);

    float4 bs = ((const float4*)b_sd)[lane];
    float4 bd = ((const float4*)b_ds)[lane];
    float4 o;
    o.x = acc.x + ALPHA * bs.x + (1.0f - ALPHA) * bd.x;
    o.y = acc.y + ALPHA * bs.y + (1.0f - ALPHA) * bd.y;
    o.z = acc.z + ALPHA * bs.z + (1.0f - ALPHA) * bd.z;
    o.w = acc.w + ALPHA * bs.w + (1.0f - ALPHA) * bd.w;
    ((float4*)out)[n * D4 + lane] = o;
}

// ---------------- launch ----------------
// Fork-join identical to the proven R8 structure: init on main stream, gemm
// forked onto side stream after init, prep chain on main, join before gather.

static cudaStream_t g_s2  = 0;
static cudaEvent_t  g_evA = 0, g_evB = 0;

extern "C" void kernel_launch(void* const* d_in, const int* in_sizes, int n_in,
                              void* d_out, int out_size) {
    const float* x    = (const float*)d_in[0];
    const float* Wsd  = (const float*)d_in[1];
    const float* b_sd = (const float*)d_in[2];
    const float* Wds  = (const float*)d_in[3];
    const float* b_ds = (const float*)d_in[4];
    const int*   ei   = (const int*)  d_in[5];
    float* out = (float*)d_out;

    int N = in_sizes[0] / D;
    int E = in_sizes[5] / 2;

    if (!g_s2) {
        cudaStreamCreateWithFlags(&g_s2, cudaStreamNonBlocking);
        cudaEventCreateWithFlags(&g_evA, cudaEventDisableTiming);
        cudaEventCreateWithFlags(&g_evB, cudaEventDisableTiming);
    }

    size_t smem = (size_t)(256 + 192) * LDH * sizeof(__half);   // 93184 B
    cudaFuncSetAttribute(gemm_mma_kernel,
                         cudaFuncAttributeMaxDynamicSharedMemorySize, (int)smem);

    int nScan = (N + 255) / 256;

    init_kernel<<<(N + 255) / 256, 256>>>(Wsd, Wds, N);

    // fork: gemm depends only on init
    cudaEventRecord(g_evA, 0);
    cudaStreamWaitEvent(g_s2, g_evA, 0);
    gemm_mma_kernel<<<(N + 255) / 256, 256, smem, g_s2>>>(x, N);
    cudaEventRecord(g_evB, g_s2);

    // graph prep on main stream (overlaps with gemm)
    deg_kernel  <<<(E + 2047) / 2048, 256>>>(ei, E);
    scanA_kernel<<<nScan, 256>>>(N);
    build_kernel<<<(E / 4 + 255) / 256 + 1, 256>>>(ei, E);

    // join: gather needs both
    cudaStreamWaitEvent(0, g_evB, 0);
    long long gthreads = (long long)N * 32;
    gather_kernel<<<(int)((gthreads + 255) / 256), 256>>>(out, b_sd, b_ds, N);
}